// round 14
// baseline (speedup 1.0000x reference)
#include <cuda_runtime.h>
#include <cuda_fp16.h>
#include <cstdint>

#define N_USERS 40000
#define N_ITEMS 60000
#define N_NODES 100000
#define IN_DIM 256
#define HID 256
#define M_EDGES 500000
#define BB 4096
#define NUM_LAYERS 5
#define ROUTIT 7
#define EPS 1e-12f
#define FULL 0xffffffffu
#define STRIDE 96          // CSR slots per user (P(overflow) ~ 0)

typedef unsigned long long ull;

// ---------------- packed f32x2 + misc helpers --------------------------------
__device__ __forceinline__ ull fma2(ull a, ull b, ull c) {
    ull d; asm("fma.rn.f32x2 %0, %1, %2, %3;" : "=l"(d) : "l"(a), "l"(b), "l"(c)); return d;
}
__device__ __forceinline__ ull mul2(ull a, ull b) {
    ull d; asm("mul.rn.f32x2 %0, %1, %2;" : "=l"(d) : "l"(a), "l"(b)); return d;
}
__device__ __forceinline__ ull add2(ull a, ull b) {
    ull d; asm("add.rn.f32x2 %0, %1, %2;" : "=l"(d) : "l"(a), "l"(b)); return d;
}
__device__ __forceinline__ float hsum2(ull v) {
    float lo, hi; asm("mov.b64 {%0, %1}, %2;" : "=f"(lo), "=f"(hi) : "l"(v)); return lo + hi;
}
__device__ __forceinline__ ull packf2(float x, float y) {
    ull r; asm("mov.b64 %0, {%1, %2};" : "=l"(r) : "f"(x), "f"(y)); return r;
}
__device__ __forceinline__ float rcpa(float x) {
    float r; asm("rcp.approx.f32 %0, %1;" : "=f"(r) : "f"(x)); return r;
}
__device__ __forceinline__ float rsqrta(float x) {
    float r; asm("rsqrt.approx.f32 %0, %1;" : "=f"(r) : "f"(x)); return r;
}
__device__ __forceinline__ float ex2a(float x) {
    float r; asm("ex2.approx.f32 %0, %1;" : "=f"(r) : "f"(x)); return r;
}
#define LOG2E 1.44269504f

// half2 bits <-> float2-as-ull
__device__ __forceinline__ ull h2_to_f2(unsigned bits) {
    __half2 h = *reinterpret_cast<const __half2*>(&bits);
    float2 f = __half22float2(h);
    return packf2(f.x, f.y);
}
__device__ __forceinline__ unsigned f2_to_h2(ull v) {
    float lo, hi; asm("mov.b64 {%0, %1}, %2;" : "=f"(lo), "=f"(hi) : "l"(v));
    __half2 h = __floats2half2_rn(lo, hi);
    return *reinterpret_cast<unsigned*>(&h);
}

// permutation: element j (k=j/32, d=j%32) -> lane l=4k+d/8 holds 8 contiguous dims.
__device__ __forceinline__ int fpos(int j) {
    int k = j >> 5, d = j & 31;
    int l = (k << 2) + (d >> 3);
    int jj = d & 7;
    return (jj < 4) ? (4 * l + jj) : (128 + 4 * l + (jj - 4));
}

// ---------------- scratch ----------------------------------------------------
__device__ float g_Zp[(size_t)N_NODES * HID];
__device__ int   g_deg[N_USERS];
__device__ int   g_ctrg[(size_t)N_USERS * STRIDE];
__device__ int   g_uorder[N_USERS];

// ---------------- GEMM: Zp = perm(l2norm(relu(X@W + b))); also zeros g_deg ---
#define RPB 32
__global__ void __launch_bounds__(128)
gemm_init_kernel(const float* __restrict__ X,
                 const float* __restrict__ W,
                 const float* __restrict__ b,
                 float* __restrict__ Zp)
{
    {
        int gid = blockIdx.x * blockDim.x + threadIdx.x;
        if (gid < N_USERS) g_deg[gid] = 0;
    }

    __shared__ ull xs2[RPB / 2][IN_DIM];
    int t = threadIdx.x;
    int j0 = t, j1 = t + 128;
    int row0 = blockIdx.x * RPB;

    for (int idx = t; idx < (RPB / 2) * IN_DIM; idx += 128) {
        int rp = idx >> 8, i = idx & 255;
        float a = X[(size_t)(row0 + 2 * rp) * IN_DIM + i];
        float c = X[(size_t)(row0 + 2 * rp + 1) * IN_DIM + i];
        xs2[rp][i] = packf2(a, c);
    }
    __syncthreads();

    float b0 = b[j0], b1 = b[j1];
    ull acc0[RPB / 2], acc1[RPB / 2];
#pragma unroll
    for (int rp = 0; rp < RPB / 2; rp++) { acc0[rp] = packf2(b0, b0); acc1[rp] = packf2(b1, b1); }

#pragma unroll 4
    for (int i = 0; i < IN_DIM; i++) {
        float w0 = W[(size_t)i * HID + j0];
        float w1 = W[(size_t)i * HID + j1];
        ull wp0 = packf2(w0, w0), wp1 = packf2(w1, w1);
#pragma unroll
        for (int rp = 0; rp < RPB / 2; rp++) {
            ull x = xs2[rp][i];
            acc0[rp] = fma2(x, wp0, acc0[rp]);
            acc1[rp] = fma2(x, wp1, acc1[rp]);
        }
    }

    int f0 = fpos(j0), f1 = fpos(j1);
#pragma unroll
    for (int rp = 0; rp < RPB / 2; rp++) {
        float va[2], vb[2];
        asm("mov.b64 {%0, %1}, %2;" : "=f"(va[0]), "=f"(va[1]) : "l"(acc0[rp]));
        asm("mov.b64 {%0, %1}, %2;" : "=f"(vb[0]), "=f"(vb[1]) : "l"(acc1[rp]));
#pragma unroll
        for (int h = 0; h < 2; h++) {
            float h0 = fmaxf(va[h], 0.f);
            float h1 = fmaxf(vb[h], 0.f);
            float s0 = h0 * h0, s1 = h1 * h1;
#pragma unroll
            for (int o = 16; o > 0; o >>= 1) {
                s0 += __shfl_xor_sync(FULL, s0, o);
                s1 += __shfl_xor_sync(FULL, s1, o);
            }
            float i0 = rcpa(fmaxf(sqrtf(s0), EPS));
            float i1 = rcpa(fmaxf(sqrtf(s1), EPS));
            size_t rowoff = (size_t)(row0 + 2 * rp + h) * HID;
            Zp[rowoff + f0] = h0 * i0;
            Zp[rowoff + f1] = h1 * i1;
        }
    }
}

// ---------------- CSR build (strided; no scan) -------------------------------
__global__ void hist_scatter_kernel(const int* __restrict__ src,
                                    const int* __restrict__ trg)
{
    int i = blockIdx.x * blockDim.x + threadIdx.x;
    if (i < M_EDGES) {
        int s = src[i];
        int pos = atomicAdd(&g_deg[s], 1);
        if (pos < STRIDE) g_ctrg[(size_t)s * STRIDE + pos] = trg[i];
    }
}

// fused counting sort of users by degree (descending), single block
__global__ void __launch_bounds__(1024)
sort_fused_kernel()
{
    __shared__ int bins[64];
    __shared__ int bcur[64];
    int tid = threadIdx.x;
    if (tid < 64) bins[tid] = 0;
    __syncthreads();
    for (int u = tid; u < N_USERS; u += 1024) {
        int d = g_deg[u];
        int bin = 63 - (d < 63 ? d : 63);
        atomicAdd(&bins[bin], 1);
    }
    __syncthreads();
    if (tid < 64) bcur[tid] = bins[tid];
    __syncthreads();
    for (int o = 1; o < 64; o <<= 1) {
        int v = 0;
        if (tid < 64 && tid >= o) v = bcur[tid - o];
        __syncthreads();
        if (tid < 64) bcur[tid] += v;
        __syncthreads();
    }
    if (tid < 64) {
        int incl = bcur[tid];
        __syncthreads();
        bcur[tid] = incl - bins[tid];
    } else {
        __syncthreads();
    }
    __syncthreads();
    for (int u = tid; u < N_USERS; u += 1024) {
        int d = g_deg[u];
        int bin = 63 - (d < 63 ? d : 63);
        int p = atomicAdd(&bcur[bin], 1);
        g_uorder[p] = u;
    }
}

// ---------------- mega routing kernel ----------------------------------------
#define SLOTS 16                       // fp16 rows per warp (512B each)
#define GPLANE 264                     // halves per k-plane of G (16*16 + 8 pad)
#define WARP_SMEM_BYTES (SLOTS * 512 + 8 * GPLANE * 2)   // 8192 + 4224 = 12416

__device__ __forceinline__ void load_row_g(const float* __restrict__ Zp, int node,
                                           int lane, ull X[4])
{
    const ulonglong2* p = reinterpret_cast<const ulonglong2*>(Zp + (size_t)node * HID);
    ulonglong2 a = p[lane];
    ulonglong2 c = p[32 + lane];
    X[0] = a.x; X[1] = a.y; X[2] = c.x; X[3] = c.y;
}

__device__ __forceinline__ void load_row_h(const uint4* rows, int slot, int lane, ull X[4])
{
    uint4 h = rows[slot * 32 + lane];
    X[0] = h2_to_f2(h.x);
    X[1] = h2_to_f2(h.y);
    X[2] = h2_to_f2(h.z);
    X[3] = h2_to_f2(h.w);
}

// transposed quad dot: lane (4k+sub) returns full dot_k(row_sub, v)
__device__ __forceinline__ float quad_dot_t(const ull A[4], const ull B[4],
                                            const ull C[4], const ull D[4],
                                            const ull v2[4], int sub)
{
    ull s0 = mul2(A[0], v2[0]);
    ull s1 = mul2(B[0], v2[0]);
    ull s2 = mul2(C[0], v2[0]);
    ull s3 = mul2(D[0], v2[0]);
#pragma unroll
    for (int q = 1; q < 4; q++) {
        s0 = fma2(A[q], v2[q], s0);
        s1 = fma2(B[q], v2[q], s1);
        s2 = fma2(C[q], v2[q], s2);
        s3 = fma2(D[q], v2[q], s3);
    }
    float p0 = hsum2(s0), p1 = hsum2(s1), p2 = hsum2(s2), p3 = hsum2(s3);
    bool b0 = sub & 1, b1 = sub & 2;
    float sA = b0 ? p0 : p1;
    float sB = b0 ? p2 : p3;
    float rA = __shfl_xor_sync(FULL, sA, 1);
    float rB = __shfl_xor_sync(FULL, sB, 1);
    float q0 = (b0 ? p1 : p0) + rA;
    float q1 = (b0 ? p3 : p2) + rB;
    float sC = b1 ? q0 : q1;
    float rC = __shfl_xor_sync(FULL, sC, 2);
    return (b1 ? q1 : q0) + rC;
}

// classic-path quad (dot + softmax + agg), as R13
__device__ __forceinline__ void edge_quad_t(const ull A[4], const ull B[4],
                                            const ull C[4], const ull D[4],
                                            const ull c2[4], int sub,
                                            ull aggA[4], ull aggB[4])
{
    float S = quad_dot_t(A, B, C, D, c2, sub);
    float e = ex2a(S * LOG2E);
    float den = e;
    den += __shfl_xor_sync(FULL, den, 4);
    den += __shfl_xor_sync(FULL, den, 8);
    den += __shfl_xor_sync(FULL, den, 16);
    float w = e * rcpa(den);
    float w0 = __shfl_sync(FULL, w, 0, 4);
    float w1 = __shfl_sync(FULL, w, 1, 4);
    float w2 = __shfl_sync(FULL, w, 2, 4);
    float w3 = __shfl_sync(FULL, w, 3, 4);
    ull w02 = packf2(w0, w0), w12 = packf2(w1, w1);
    ull w22 = packf2(w2, w2), w32 = packf2(w3, w3);
#pragma unroll
    for (int q = 0; q < 4; q++) {
        aggA[q] = fma2(A[q], w02, aggA[q]);
        aggB[q] = fma2(B[q], w12, aggB[q]);
        aggA[q] = fma2(C[q], w22, aggA[q]);
        aggB[q] = fma2(D[q], w32, aggB[q]);
    }
}

__device__ __forceinline__ void edge_pair(const ull A[4], const ull B[4],
                                          const ull c2[4],
                                          ull aggA[4], ull aggB[4])
{
    ull sa2 = mul2(A[0], c2[0]);
    ull sb2 = mul2(B[0], c2[0]);
#pragma unroll
    for (int q = 1; q < 4; q++) {
        sa2 = fma2(A[q], c2[q], sa2);
        sb2 = fma2(B[q], c2[q], sb2);
    }
    float sa = hsum2(sa2), sb = hsum2(sb2);
    sa += __shfl_xor_sync(FULL, sa, 1);  sb += __shfl_xor_sync(FULL, sb, 1);
    sa += __shfl_xor_sync(FULL, sa, 2);  sb += __shfl_xor_sync(FULL, sb, 2);
    float ea = ex2a(sa * LOG2E), eb = ex2a(sb * LOG2E);
    float da = ea, db = eb;
    da += __shfl_xor_sync(FULL, da, 4);   db += __shfl_xor_sync(FULL, db, 4);
    da += __shfl_xor_sync(FULL, da, 8);   db += __shfl_xor_sync(FULL, db, 8);
    da += __shfl_xor_sync(FULL, da, 16);  db += __shfl_xor_sync(FULL, db, 16);
    float wa = ea * rcpa(da), wb = eb * rcpa(db);
    ull wa2 = packf2(wa, wa), wb2 = packf2(wb, wb);
#pragma unroll
    for (int q = 0; q < 4; q++) {
        aggA[q] = fma2(A[q], wa2, aggA[q]);
        aggB[q] = fma2(B[q], wb2, aggB[q]);
    }
}

__device__ __forceinline__ void edge_one(const ull A[4], const ull c2[4], ull aggA[4])
{
    ull sa2 = mul2(A[0], c2[0]);
#pragma unroll
    for (int q = 1; q < 4; q++) sa2 = fma2(A[q], c2[q], sa2);
    float sa = hsum2(sa2);
    sa += __shfl_xor_sync(FULL, sa, 1);
    sa += __shfl_xor_sync(FULL, sa, 2);
    float ea = ex2a(sa * LOG2E);
    float da = ea;
    da += __shfl_xor_sync(FULL, da, 4);
    da += __shfl_xor_sync(FULL, da, 8);
    da += __shfl_xor_sync(FULL, da, 16);
    float wa = ea * rcpa(da);
    ull wa2 = packf2(wa, wa);
#pragma unroll
    for (int q = 0; q < 4; q++) aggA[q] = fma2(A[q], wa2, aggA[q]);
}

extern __shared__ char sh_raw[];   // 4 warps * 12416B = 49664B

__global__ void __launch_bounds__(128, 4)
route_all_kernel(float* __restrict__ Zp)
{
    int lane = threadIdx.x & 31;
    int winb = threadIdx.x >> 5;
    int sub  = lane & 3;
    int k    = lane >> 2;
    int u = g_uorder[blockIdx.x * 4 + winb];
    char* wbase = sh_raw + (size_t)winb * WARP_SMEM_BYTES;
    uint4* rows = reinterpret_cast<uint4*>(wbase);
    __half* G = reinterpret_cast<__half*>(wbase + SLOTS * 512);
    unsigned* Gw = reinterpret_cast<unsigned*>(G);
    const uint4* Gu4 = reinterpret_cast<const uint4*>(G);

    int beg = u * STRIDE;
    int deg = g_deg[u];
    if (deg > STRIDE) deg = STRIDE;

    ull z2[4];
    load_row_g(Zp, u, lane, z2);

    if (deg <= SLOTS) {
        // ==================== GRAM PATH ====================
        int E = deg;
        // fill fp16 rows; zero-pad unused slots
        for (int e = 0; e < SLOTS; e++) {
            uint4 h;
            if (e < E) {
                int t = g_ctrg[beg + e];
                ull X[4];
                load_row_g(Zp, t, lane, X);
                h.x = f2_to_h2(X[0]); h.y = f2_to_h2(X[1]);
                h.z = f2_to_h2(X[2]); h.w = f2_to_h2(X[3]);
            } else {
                h = make_uint4(0, 0, 0, 0);
            }
            rows[e * 32 + lane] = h;
        }
        // zero G (incl. padding)
        for (int i = lane; i < (8 * GPLANE * 2) / 4; i += 32) Gw[i] = 0;
        __syncwarp();
        // build G: for each edge e, dot vs all 16 slots (zero rows -> 0)
        for (int e = 0; e < E; e++) {
            ull R[4];
            load_row_h(rows, e, lane, R);
#pragma unroll
            for (int j2 = 0; j2 < 4; j2++) {
                ull A[4], B[4], C[4], D[4];
                load_row_h(rows, 4 * j2 + 0, lane, A);
                load_row_h(rows, 4 * j2 + 1, lane, B);
                load_row_h(rows, 4 * j2 + 2, lane, C);
                load_row_h(rows, 4 * j2 + 3, lane, D);
                float S = quad_dot_t(A, B, C, D, R, sub);
                G[k * GPLANE + e * 16 + 4 * j2 + sub] = __float2half(S);
            }
        }
        __syncwarp();

        float w[4], a[4], vm[4];
#pragma unroll
        for (int j = 0; j < 4; j++) vm[j] = (4 * j + sub < E) ? 1.f : 0.f;

        for (int layer = 0; layer < NUM_LAYERS; layer++) {
            // a_ek = dot_k(zt_e, z)
#pragma unroll
            for (int j = 0; j < 4; j++) {
                ull A[4], B[4], C[4], D[4];
                load_row_h(rows, 4 * j + 0, lane, A);
                load_row_h(rows, 4 * j + 1, lane, B);
                load_row_h(rows, 4 * j + 2, lane, C);
                load_row_h(rows, 4 * j + 3, lane, D);
                a[j] = quad_dot_t(A, B, C, D, z2, sub);
            }
            for (int it = 0; it < ROUTIT; it++) {
                float s[4];
                if (it == 0) {
#pragma unroll
                    for (int j = 0; j < 4; j++) s[j] = a[j];
                } else {
                    // load this lane's 4 G rows (16 halves each)
                    unsigned g[4][8];
#pragma unroll
                    for (int j = 0; j < 4; j++) {
                        uint4 ga = Gu4[k * 33 + (4 * j + sub) * 2];
                        uint4 gb = Gu4[k * 33 + (4 * j + sub) * 2 + 1];
                        g[j][0] = ga.x; g[j][1] = ga.y; g[j][2] = ga.z; g[j][3] = ga.w;
                        g[j][4] = gb.x; g[j][5] = gb.y; g[j][6] = gb.z; g[j][7] = gb.w;
                    }
                    // t_ek = sum_e' w_e'k G_k[e,e']
                    ull t2[4] = {0, 0, 0, 0};
#pragma unroll
                    for (int p = 0; p < 8; p++) {
                        float wlo = __shfl_sync(FULL, w[p >> 1], (p & 1) * 2,     4);
                        float whi = __shfl_sync(FULL, w[p >> 1], (p & 1) * 2 + 1, 4);
                        ull wb2 = packf2(wlo, whi);
#pragma unroll
                        for (int j = 0; j < 4; j++)
                            t2[j] = fma2(h2_to_f2(g[j][p]), wb2, t2[j]);
                    }
                    float t[4];
#pragma unroll
                    for (int j = 0; j < 4; j++) t[j] = hsum2(t2[j]);
                    // n_k^2 = 1 + sum_e w(2a + t)
                    float acc = 0.f;
#pragma unroll
                    for (int j = 0; j < 4; j++) acc = fmaf(w[j], 2.f * a[j] + t[j], acc);
                    acc += __shfl_xor_sync(FULL, acc, 1);
                    acc += __shfl_xor_sync(FULL, acc, 2);
                    float invn = rsqrta(1.f + acc);
#pragma unroll
                    for (int j = 0; j < 4; j++) s[j] = (a[j] + t[j]) * invn;
                }
                // softmax over k (stride-4 lanes share an edge)
#pragma unroll
                for (int j = 0; j < 4; j++) {
                    float e1 = ex2a(s[j] * LOG2E);
                    float den = e1;
                    den += __shfl_xor_sync(FULL, den, 4);
                    den += __shfl_xor_sync(FULL, den, 8);
                    den += __shfl_xor_sync(FULL, den, 16);
                    w[j] = vm[j] * e1 * rcpa(den);
                }
            }
            // materialize c -> z2
            ull agg[4] = {0, 0, 0, 0};
#pragma unroll
            for (int e = 0; e < SLOTS; e++) {
                float wb = __shfl_sync(FULL, w[e >> 2], e & 3, 4);
                ull X[4];
                load_row_h(rows, e, lane, X);
                ull wb2 = packf2(wb, wb);
#pragma unroll
                for (int q = 0; q < 4; q++) agg[q] = fma2(X[q], wb2, agg[q]);
            }
            ull v[4];
#pragma unroll
            for (int q = 0; q < 4; q++) v[q] = add2(z2[q], agg[q]);
            ull n2 = mul2(v[0], v[0]);
#pragma unroll
            for (int q = 1; q < 4; q++) n2 = fma2(v[q], v[q], n2);
            float nn = hsum2(n2);
            nn += __shfl_xor_sync(FULL, nn, 1);
            nn += __shfl_xor_sync(FULL, nn, 2);
            float r = rsqrta(nn);
            ull r2 = packf2(r, r);
#pragma unroll
            for (int q = 0; q < 4; q++) z2[q] = mul2(v[q], r2);
        }
        ulonglong2* p = reinterpret_cast<ulonglong2*>(Zp + (size_t)u * HID);
        p[lane]      = make_ulonglong2(z2[0], z2[1]);
        p[32 + lane] = make_ulonglong2(z2[2], z2[3]);
    } else {
        // ==================== CLASSIC PATH (deg > 16) ====================
        for (int e = 0; e < SLOTS; e++) {
            int t = g_ctrg[beg + e];
            ull X[4];
            load_row_g(Zp, t, lane, X);
            uint4 h;
            h.x = f2_to_h2(X[0]); h.y = f2_to_h2(X[1]);
            h.z = f2_to_h2(X[2]); h.w = f2_to_h2(X[3]);
            rows[e * 32 + lane] = h;
        }
        ull c2[4];
#pragma unroll
        for (int q = 0; q < 4; q++) c2[q] = z2[q];

        for (int layer = 0; layer < NUM_LAYERS; layer++) {
            for (int it = 0; it < ROUTIT; it++) {
                ull aggA[4] = {0, 0, 0, 0};
                ull aggB[4] = {0, 0, 0, 0};
#pragma unroll
                for (int eb = 0; eb < SLOTS; eb += 4) {
                    ull A[4], B[4], C[4], D[4];
                    load_row_h(rows, eb + 0, lane, A);
                    load_row_h(rows, eb + 1, lane, B);
                    load_row_h(rows, eb + 2, lane, C);
                    load_row_h(rows, eb + 3, lane, D);
                    edge_quad_t(A, B, C, D, c2, sub, aggA, aggB);
                }
                int eg = SLOTS;
                for (; eg + 1 < deg; eg += 2) {
                    ull A[4], B[4];
                    load_row_g(Zp, g_ctrg[beg + eg],     lane, A);
                    load_row_g(Zp, g_ctrg[beg + eg + 1], lane, B);
                    edge_pair(A, B, c2, aggA, aggB);
                }
                if (eg < deg) {
                    ull A[4];
                    load_row_g(Zp, g_ctrg[beg + eg], lane, A);
                    edge_one(A, c2, aggA);
                }
                ull v[4];
#pragma unroll
                for (int q = 0; q < 4; q++) v[q] = add2(z2[q], add2(aggA[q], aggB[q]));
                ull n2 = mul2(v[0], v[0]);
#pragma unroll
                for (int q = 1; q < 4; q++) n2 = fma2(v[q], v[q], n2);
                float nn = hsum2(n2);
                nn += __shfl_xor_sync(FULL, nn, 1);
                nn += __shfl_xor_sync(FULL, nn, 2);
                float r = rsqrta(nn);
                ull r2 = packf2(r, r);
#pragma unroll
                for (int q = 0; q < 4; q++) c2[q] = mul2(v[q], r2);
            }
#pragma unroll
            for (int q = 0; q < 4; q++) z2[q] = c2[q];
        }
        ulonglong2* p = reinterpret_cast<ulonglong2*>(Zp + (size_t)u * HID);
        p[lane]      = make_ulonglong2(c2[0], c2[1]);
        p[32 + lane] = make_ulonglong2(c2[2], c2[3]);
    }
}

// ---------------- output gather (un-permute) ---------------------------------
__global__ void gather_kernel(const int* __restrict__ users,
                              const int* __restrict__ pos,
                              const int* __restrict__ neg,
                              const float* __restrict__ Zp,
                              float* __restrict__ out)
{
    int r = blockIdx.x;
    int j = threadIdx.x;
    int node;
    if (r < BB)            node = users[r];
    else if (r < 2 * BB)   node = N_USERS + pos[r - BB];
    else                   node = N_USERS + neg[r - 2 * BB];
    out[(size_t)r * HID + j] = Zp[(size_t)node * HID + fpos(j)];
}

// ---------------- launch -----------------------------------------------------
extern "C" void kernel_launch(void* const* d_in, const int* in_sizes, int n_in,
                              void* d_out, int out_size)
{
    const float* X     = (const float*)d_in[0];
    const float* W     = (const float*)d_in[1];
    const float* b     = (const float*)d_in[2];
    const int*   edges = (const int*)d_in[3];
    const int*   users = (const int*)d_in[4];
    const int*   pos   = (const int*)d_in[5];
    const int*   neg   = (const int*)d_in[6];
    float*       out   = (float*)d_out;
    const int* src = edges;
    const int* trg = edges + M_EDGES;

    float* Zp = nullptr;
    cudaGetSymbolAddress((void**)&Zp, g_Zp);

    const int routeSmem = 4 * WARP_SMEM_BYTES;   // 49664 B
    cudaFuncSetAttribute(route_all_kernel,
                         cudaFuncAttributeMaxDynamicSharedMemorySize, routeSmem);

    // launch order keeps route_all_kernel as the 4th launch (ncu target)
    gemm_init_kernel<<<N_NODES / RPB, 128>>>(X, W, b, Zp);         // 1 (also zeros g_deg)
    hist_scatter_kernel<<<(M_EDGES + 255) / 256, 256>>>(src, trg);  // 2
    sort_fused_kernel<<<1, 1024>>>();                               // 3
    route_all_kernel<<<N_USERS / 4, 128, routeSmem>>>(Zp);          // 4  <-- profiled
    gather_kernel<<<3 * BB, 256>>>(users, pos, neg, Zp, out);       // 5
}

// round 15
// speedup vs baseline: 1.1605x; 1.1605x over previous
#include <cuda_runtime.h>
#include <cstdint>

#define N_USERS 40000
#define N_ITEMS 60000
#define N_NODES 100000
#define IN_DIM 256
#define HID 256
#define M_EDGES 500000
#define BB 4096
#define NUM_LAYERS 5
#define ROUTIT 7
#define EPS 1e-12f
#define FULL 0xffffffffu
#define STRIDE 96          // CSR slots per user (P(overflow) ~ 0)

typedef unsigned long long ull;

// ---------------- packed f32x2 + misc helpers --------------------------------
__device__ __forceinline__ ull fma2(ull a, ull b, ull c) {
    ull d; asm("fma.rn.f32x2 %0, %1, %2, %3;" : "=l"(d) : "l"(a), "l"(b), "l"(c)); return d;
}
__device__ __forceinline__ ull mul2(ull a, ull b) {
    ull d; asm("mul.rn.f32x2 %0, %1, %2;" : "=l"(d) : "l"(a), "l"(b)); return d;
}
__device__ __forceinline__ ull add2(ull a, ull b) {
    ull d; asm("add.rn.f32x2 %0, %1, %2;" : "=l"(d) : "l"(a), "l"(b)); return d;
}
__device__ __forceinline__ float hsum2(ull v) {
    float lo, hi; asm("mov.b64 {%0, %1}, %2;" : "=f"(lo), "=f"(hi) : "l"(v)); return lo + hi;
}
__device__ __forceinline__ ull packf2(float x, float y) {
    ull r; asm("mov.b64 %0, {%1, %2};" : "=l"(r) : "f"(x), "f"(y)); return r;
}
__device__ __forceinline__ float rcpa(float x) {
    float r; asm("rcp.approx.f32 %0, %1;" : "=f"(r) : "f"(x)); return r;
}
__device__ __forceinline__ float rsqrta(float x) {
    float r; asm("rsqrt.approx.f32 %0, %1;" : "=f"(r) : "f"(x)); return r;
}
__device__ __forceinline__ float ex2a(float x) {
    float r; asm("ex2.approx.f32 %0, %1;" : "=f"(r) : "f"(x)); return r;
}
#define LOG2E 1.44269504f

// permutation: element j (k=j/32, d=j%32) -> lane l=4k+d/8 holds 8 contiguous dims.
__device__ __forceinline__ int fpos(int j) {
    int k = j >> 5, d = j & 31;
    int l = (k << 2) + (d >> 3);
    int jj = d & 7;
    return (jj < 4) ? (4 * l + jj) : (128 + 4 * l + (jj - 4));
}

// ---------------- scratch ----------------------------------------------------
__device__ float g_Zp[(size_t)N_NODES * HID];
__device__ int   g_deg[N_USERS];
__device__ int   g_ctrg[(size_t)N_USERS * STRIDE];
__device__ int   g_uorder[N_USERS];

// ---------------- GEMM: Zp = perm(l2norm(relu(X@W + b))); also zeros g_deg ---
#define RPB 32
__global__ void __launch_bounds__(128)
gemm_init_kernel(const float* __restrict__ X,
                 const float* __restrict__ W,
                 const float* __restrict__ b,
                 float* __restrict__ Zp)
{
    {
        int gid = blockIdx.x * blockDim.x + threadIdx.x;
        if (gid < N_USERS) g_deg[gid] = 0;
    }

    __shared__ ull xs2[RPB / 2][IN_DIM];
    int t = threadIdx.x;
    int j0 = t, j1 = t + 128;
    int row0 = blockIdx.x * RPB;

    for (int idx = t; idx < (RPB / 2) * IN_DIM; idx += 128) {
        int rp = idx >> 8, i = idx & 255;
        float a = X[(size_t)(row0 + 2 * rp) * IN_DIM + i];
        float c = X[(size_t)(row0 + 2 * rp + 1) * IN_DIM + i];
        xs2[rp][i] = packf2(a, c);
    }
    __syncthreads();

    float b0 = b[j0], b1 = b[j1];
    ull acc0[RPB / 2], acc1[RPB / 2];
#pragma unroll
    for (int rp = 0; rp < RPB / 2; rp++) { acc0[rp] = packf2(b0, b0); acc1[rp] = packf2(b1, b1); }

#pragma unroll 4
    for (int i = 0; i < IN_DIM; i++) {
        float w0 = W[(size_t)i * HID + j0];
        float w1 = W[(size_t)i * HID + j1];
        ull wp0 = packf2(w0, w0), wp1 = packf2(w1, w1);
#pragma unroll
        for (int rp = 0; rp < RPB / 2; rp++) {
            ull x = xs2[rp][i];
            acc0[rp] = fma2(x, wp0, acc0[rp]);
            acc1[rp] = fma2(x, wp1, acc1[rp]);
        }
    }

    int f0 = fpos(j0), f1 = fpos(j1);
#pragma unroll
    for (int rp = 0; rp < RPB / 2; rp++) {
        float va[2], vb[2];
        asm("mov.b64 {%0, %1}, %2;" : "=f"(va[0]), "=f"(va[1]) : "l"(acc0[rp]));
        asm("mov.b64 {%0, %1}, %2;" : "=f"(vb[0]), "=f"(vb[1]) : "l"(acc1[rp]));
#pragma unroll
        for (int h = 0; h < 2; h++) {
            float h0 = fmaxf(va[h], 0.f);
            float h1 = fmaxf(vb[h], 0.f);
            float s0 = h0 * h0, s1 = h1 * h1;
#pragma unroll
            for (int o = 16; o > 0; o >>= 1) {
                s0 += __shfl_xor_sync(FULL, s0, o);
                s1 += __shfl_xor_sync(FULL, s1, o);
            }
            float i0 = rcpa(fmaxf(sqrtf(s0), EPS));
            float i1 = rcpa(fmaxf(sqrtf(s1), EPS));
            size_t rowoff = (size_t)(row0 + 2 * rp + h) * HID;
            Zp[rowoff + f0] = h0 * i0;
            Zp[rowoff + f1] = h1 * i1;
        }
    }
}

// ---------------- CSR build (strided; no scan) -------------------------------
__global__ void hist_scatter_kernel(const int* __restrict__ src,
                                    const int* __restrict__ trg)
{
    int i = blockIdx.x * blockDim.x + threadIdx.x;
    if (i < M_EDGES) {
        int s = src[i];
        int pos = atomicAdd(&g_deg[s], 1);
        if (pos < STRIDE) g_ctrg[(size_t)s * STRIDE + pos] = trg[i];
    }
}

// fused counting sort of users by degree (descending), single block.
// g_deg staged through smem: one coalesced global read instead of two.
__global__ void __launch_bounds__(1024)
sort_fused_kernel()
{
    extern __shared__ int sh_sort[];          // N_USERS ints (160KB)
    __shared__ int bins[64];
    __shared__ int bcur[64];
    int tid = threadIdx.x;
    if (tid < 64) bins[tid] = 0;
    for (int u = tid; u < N_USERS; u += 1024) sh_sort[u] = g_deg[u];
    __syncthreads();
    for (int u = tid; u < N_USERS; u += 1024) {
        int d = sh_sort[u];
        int bin = 63 - (d < 63 ? d : 63);
        atomicAdd(&bins[bin], 1);
    }
    __syncthreads();
    if (tid < 64) bcur[tid] = bins[tid];
    __syncthreads();
    for (int o = 1; o < 64; o <<= 1) {
        int v = 0;
        if (tid < 64 && tid >= o) v = bcur[tid - o];
        __syncthreads();
        if (tid < 64) bcur[tid] += v;
        __syncthreads();
    }
    if (tid < 64) {
        int incl = bcur[tid];
        __syncthreads();
        bcur[tid] = incl - bins[tid];
    } else {
        __syncthreads();
    }
    __syncthreads();
    for (int u = tid; u < N_USERS; u += 1024) {
        int d = sh_sort[u];
        int bin = 63 - (d < 63 ? d : 63);
        int p = atomicAdd(&bcur[bin], 1);
        g_uorder[p] = u;
    }
}

// ---------------- mega routing kernel (R13-proven) ----------------------------
#define REGE 4
#define SLOTS 14
#define SMCAP (REGE + SLOTS)

// 4 edges; transpose-reduce so each lane owns one (k, edge) pair.
__device__ __forceinline__ void edge_quad_t(const ull A[4], const ull B[4],
                                            const ull C[4], const ull D[4],
                                            const ull c2[4], int sub,
                                            ull aggA[4], ull aggB[4])
{
    ull s0 = mul2(A[0], c2[0]);
    ull s1 = mul2(B[0], c2[0]);
    ull s2 = mul2(C[0], c2[0]);
    ull s3 = mul2(D[0], c2[0]);
#pragma unroll
    for (int q = 1; q < 4; q++) {
        s0 = fma2(A[q], c2[q], s0);
        s1 = fma2(B[q], c2[q], s1);
        s2 = fma2(C[q], c2[q], s2);
        s3 = fma2(D[q], c2[q], s3);
    }
    float p0 = hsum2(s0), p1 = hsum2(s1), p2 = hsum2(s2), p3 = hsum2(s3);
    bool b0 = sub & 1, b1 = sub & 2;
    float sA = b0 ? p0 : p1;
    float sB = b0 ? p2 : p3;
    float rA = __shfl_xor_sync(FULL, sA, 1);
    float rB = __shfl_xor_sync(FULL, sB, 1);
    float q0 = (b0 ? p1 : p0) + rA;
    float q1 = (b0 ? p3 : p2) + rB;
    float sC = b1 ? q0 : q1;
    float rC = __shfl_xor_sync(FULL, sC, 2);
    float S  = (b1 ? q1 : q0) + rC;
    float e = ex2a(S * LOG2E);
    float den = e;
    den += __shfl_xor_sync(FULL, den, 4);
    den += __shfl_xor_sync(FULL, den, 8);
    den += __shfl_xor_sync(FULL, den, 16);
    float w = e * rcpa(den);
    float w0 = __shfl_sync(FULL, w, 0, 4);
    float w1 = __shfl_sync(FULL, w, 1, 4);
    float w2 = __shfl_sync(FULL, w, 2, 4);
    float w3 = __shfl_sync(FULL, w, 3, 4);
    ull w02 = packf2(w0, w0), w12 = packf2(w1, w1);
    ull w22 = packf2(w2, w2), w32 = packf2(w3, w3);
#pragma unroll
    for (int q = 0; q < 4; q++) {
        aggA[q] = fma2(A[q], w02, aggA[q]);
        aggB[q] = fma2(B[q], w12, aggB[q]);
        aggA[q] = fma2(C[q], w22, aggA[q]);
        aggB[q] = fma2(D[q], w32, aggB[q]);
    }
}

// 8 edges: TWO independent transpose-reduce chains fully interleaved.
__device__ __forceinline__ void edge_oct_t(const ull A[4], const ull B[4],
                                           const ull C[4], const ull D[4],
                                           const ull E[4], const ull F[4],
                                           const ull G[4], const ull H[4],
                                           const ull c2[4], int sub,
                                           ull aggA[4], ull aggB[4])
{
    ull s0 = mul2(A[0], c2[0]);
    ull s1 = mul2(B[0], c2[0]);
    ull s2 = mul2(C[0], c2[0]);
    ull s3 = mul2(D[0], c2[0]);
    ull s4 = mul2(E[0], c2[0]);
    ull s5 = mul2(F[0], c2[0]);
    ull s6 = mul2(G[0], c2[0]);
    ull s7 = mul2(H[0], c2[0]);
#pragma unroll
    for (int q = 1; q < 4; q++) {
        s0 = fma2(A[q], c2[q], s0);
        s1 = fma2(B[q], c2[q], s1);
        s2 = fma2(C[q], c2[q], s2);
        s3 = fma2(D[q], c2[q], s3);
        s4 = fma2(E[q], c2[q], s4);
        s5 = fma2(F[q], c2[q], s5);
        s6 = fma2(G[q], c2[q], s6);
        s7 = fma2(H[q], c2[q], s7);
    }
    float p0 = hsum2(s0), p1 = hsum2(s1), p2 = hsum2(s2), p3 = hsum2(s3);
    float p4 = hsum2(s4), p5 = hsum2(s5), p6 = hsum2(s6), p7 = hsum2(s7);
    bool b0 = sub & 1, b1 = sub & 2;
    float sA = b0 ? p0 : p1;
    float sB = b0 ? p2 : p3;
    float sE = b0 ? p4 : p5;
    float sF = b0 ? p6 : p7;
    float rA = __shfl_xor_sync(FULL, sA, 1);
    float rB = __shfl_xor_sync(FULL, sB, 1);
    float rE = __shfl_xor_sync(FULL, sE, 1);
    float rF = __shfl_xor_sync(FULL, sF, 1);
    float q0 = (b0 ? p1 : p0) + rA;
    float q1 = (b0 ? p3 : p2) + rB;
    float q4 = (b0 ? p5 : p4) + rE;
    float q5 = (b0 ? p7 : p6) + rF;
    float sC = b1 ? q0 : q1;
    float sG = b1 ? q4 : q5;
    float rC = __shfl_xor_sync(FULL, sC, 2);
    float rG = __shfl_xor_sync(FULL, sG, 2);
    float S1 = (b1 ? q1 : q0) + rC;
    float S2 = (b1 ? q5 : q4) + rG;
    float e1 = ex2a(S1 * LOG2E);
    float e2 = ex2a(S2 * LOG2E);
    float d1 = e1, d2 = e2;
    d1 += __shfl_xor_sync(FULL, d1, 4);   d2 += __shfl_xor_sync(FULL, d2, 4);
    d1 += __shfl_xor_sync(FULL, d1, 8);   d2 += __shfl_xor_sync(FULL, d2, 8);
    d1 += __shfl_xor_sync(FULL, d1, 16);  d2 += __shfl_xor_sync(FULL, d2, 16);
    float w1 = e1 * rcpa(d1);
    float w2 = e2 * rcpa(d2);
    float wa = __shfl_sync(FULL, w1, 0, 4);
    float wb = __shfl_sync(FULL, w1, 1, 4);
    float wc = __shfl_sync(FULL, w1, 2, 4);
    float wd = __shfl_sync(FULL, w1, 3, 4);
    float we = __shfl_sync(FULL, w2, 0, 4);
    float wf = __shfl_sync(FULL, w2, 1, 4);
    float wg = __shfl_sync(FULL, w2, 2, 4);
    float wh = __shfl_sync(FULL, w2, 3, 4);
    ull wa2 = packf2(wa, wa), wb2 = packf2(wb, wb);
    ull wc2 = packf2(wc, wc), wd2 = packf2(wd, wd);
    ull we2 = packf2(we, we), wf2 = packf2(wf, wf);
    ull wg2 = packf2(wg, wg), wh2 = packf2(wh, wh);
#pragma unroll
    for (int q = 0; q < 4; q++) {
        aggA[q] = fma2(A[q], wa2, aggA[q]);
        aggB[q] = fma2(B[q], wb2, aggB[q]);
        aggA[q] = fma2(C[q], wc2, aggA[q]);
        aggB[q] = fma2(D[q], wd2, aggB[q]);
        aggA[q] = fma2(E[q], we2, aggA[q]);
        aggB[q] = fma2(F[q], wf2, aggB[q]);
        aggA[q] = fma2(G[q], wg2, aggA[q]);
        aggB[q] = fma2(H[q], wh2, aggB[q]);
    }
}

// 2 edges, chains interleaved (tail path)
__device__ __forceinline__ void edge_pair(const ull A[4], const ull B[4],
                                          const ull c2[4],
                                          ull aggA[4], ull aggB[4])
{
    ull sa2 = mul2(A[0], c2[0]);
    ull sb2 = mul2(B[0], c2[0]);
#pragma unroll
    for (int q = 1; q < 4; q++) {
        sa2 = fma2(A[q], c2[q], sa2);
        sb2 = fma2(B[q], c2[q], sb2);
    }
    float sa = hsum2(sa2), sb = hsum2(sb2);
    sa += __shfl_xor_sync(FULL, sa, 1);  sb += __shfl_xor_sync(FULL, sb, 1);
    sa += __shfl_xor_sync(FULL, sa, 2);  sb += __shfl_xor_sync(FULL, sb, 2);
    float ea = ex2a(sa * LOG2E), eb = ex2a(sb * LOG2E);
    float da = ea, db = eb;
    da += __shfl_xor_sync(FULL, da, 4);   db += __shfl_xor_sync(FULL, db, 4);
    da += __shfl_xor_sync(FULL, da, 8);   db += __shfl_xor_sync(FULL, db, 8);
    da += __shfl_xor_sync(FULL, da, 16);  db += __shfl_xor_sync(FULL, db, 16);
    float wa = ea * rcpa(da), wb = eb * rcpa(db);
    ull wa2 = packf2(wa, wa), wb2 = packf2(wb, wb);
#pragma unroll
    for (int q = 0; q < 4; q++) {
        aggA[q] = fma2(A[q], wa2, aggA[q]);
        aggB[q] = fma2(B[q], wb2, aggB[q]);
    }
}

// single edge (tail / overflow path)
__device__ __forceinline__ void edge_one(const ull A[4], const ull c2[4], ull aggA[4])
{
    ull sa2 = mul2(A[0], c2[0]);
#pragma unroll
    for (int q = 1; q < 4; q++) sa2 = fma2(A[q], c2[q], sa2);
    float sa = hsum2(sa2);
    sa += __shfl_xor_sync(FULL, sa, 1);
    sa += __shfl_xor_sync(FULL, sa, 2);
    float ea = ex2a(sa * LOG2E);
    float da = ea;
    da += __shfl_xor_sync(FULL, da, 4);
    da += __shfl_xor_sync(FULL, da, 8);
    da += __shfl_xor_sync(FULL, da, 16);
    float wa = ea * rcpa(da);
    ull wa2 = packf2(wa, wa);
#pragma unroll
    for (int q = 0; q < 4; q++) aggA[q] = fma2(A[q], wa2, aggA[q]);
}

__device__ __forceinline__ void load_row_g(const float* __restrict__ Zp, int node,
                                           int lane, ull X[4])
{
    const ulonglong2* p = reinterpret_cast<const ulonglong2*>(Zp + (size_t)node * HID);
    ulonglong2 a = p[lane];
    ulonglong2 c = p[32 + lane];
    X[0] = a.x; X[1] = a.y; X[2] = c.x; X[3] = c.y;
}

__device__ __forceinline__ void load_row_s(const ull* slab, int slot, int lane, ull X[4])
{
    const ulonglong2* p = reinterpret_cast<const ulonglong2*>(slab + (size_t)slot * 128);
    ulonglong2 a = p[lane], c = p[32 + lane];
    X[0] = a.x; X[1] = a.y; X[2] = c.x; X[3] = c.y;
}

extern __shared__ ull sh_slab[];   // 4 warps * SLOTS * 128 ull = 56KB

__global__ void __launch_bounds__(128, 4)
route_all_kernel(float* __restrict__ Zp)
{
    int lane = threadIdx.x & 31;
    int winb = threadIdx.x >> 5;
    int sub  = lane & 3;
    int u = g_uorder[blockIdx.x * 4 + winb];
    ull* slab = sh_slab + (size_t)winb * SLOTS * 128;

    int beg = u * STRIDE;
    int deg = g_deg[u];
    if (deg > STRIDE) deg = STRIDE;
    int nreg = deg < REGE ? deg : REGE;
    int nsm  = deg < SMCAP ? deg : SMCAP;
    int nsmem = nsm - REGE;
    if (nsmem < 0) nsmem = 0;

    ull z2[4], c2[4];
    load_row_g(Zp, u, lane, z2);

    ull er[REGE][4];
#pragma unroll
    for (int e = 0; e < REGE; e++) {
        if (e < nreg) {
            int t = g_ctrg[beg + e];
            load_row_g(Zp, t, lane, er[e]);
        }
    }
    for (int e = 0; e < nsmem; e++) {
        int t = g_ctrg[beg + REGE + e];
        ull X[4];
        load_row_g(Zp, t, lane, X);
        ulonglong2* p = reinterpret_cast<ulonglong2*>(slab + (size_t)e * 128);
        p[lane]      = make_ulonglong2(X[0], X[1]);
        p[32 + lane] = make_ulonglong2(X[2], X[3]);
    }

#pragma unroll
    for (int q = 0; q < 4; q++) c2[q] = z2[q];

    for (int layer = 0; layer < NUM_LAYERS; layer++) {
        for (int it = 0; it < ROUTIT; it++) {
            ull aggA[4] = {0, 0, 0, 0};
            ull aggB[4] = {0, 0, 0, 0};
            int e = 0;   // smem slot cursor
            if (nreg == REGE) {
                if (nsmem >= 4) {
                    ull S0[4], S1[4], S2[4], S3[4];
                    load_row_s(slab, 0, lane, S0);
                    load_row_s(slab, 1, lane, S1);
                    load_row_s(slab, 2, lane, S2);
                    load_row_s(slab, 3, lane, S3);
                    edge_oct_t(er[0], er[1], er[2], er[3],
                               S0, S1, S2, S3, c2, sub, aggA, aggB);
                    e = 4;
                } else {
                    edge_quad_t(er[0], er[1], er[2], er[3], c2, sub, aggA, aggB);
                }
            } else if (nreg == 3) {
                edge_pair(er[0], er[1], c2, aggA, aggB);
                edge_one(er[2], c2, aggA);
            } else if (nreg == 2) {
                edge_pair(er[0], er[1], c2, aggA, aggB);
            } else if (nreg == 1) {
                edge_one(er[0], c2, aggA);
            }
            for (; e + 3 < nsmem; e += 4) {
                ull A[4], B[4], C[4], D[4];
                load_row_s(slab, e,     lane, A);
                load_row_s(slab, e + 1, lane, B);
                load_row_s(slab, e + 2, lane, C);
                load_row_s(slab, e + 3, lane, D);
                edge_quad_t(A, B, C, D, c2, sub, aggA, aggB);
            }
            if (e + 1 < nsmem) {
                ull A[4], B[4];
                load_row_s(slab, e,     lane, A);
                load_row_s(slab, e + 1, lane, B);
                edge_pair(A, B, c2, aggA, aggB);
                e += 2;
            }
            if (e < nsmem) {
                ull A[4];
                load_row_s(slab, e, lane, A);
                edge_one(A, c2, aggA);
            }
            for (int eg = SMCAP; eg < deg; eg++) {
                int t = g_ctrg[beg + eg];
                ull A[4];
                load_row_g(Zp, t, lane, A);
                edge_one(A, c2, aggA);
            }
            ull v[4];
#pragma unroll
            for (int q = 0; q < 4; q++) v[q] = add2(z2[q], add2(aggA[q], aggB[q]));
            ull n2 = mul2(v[0], v[0]);
#pragma unroll
            for (int q = 1; q < 4; q++) n2 = fma2(v[q], v[q], n2);
            float n = hsum2(n2);
            n += __shfl_xor_sync(FULL, n, 1);
            n += __shfl_xor_sync(FULL, n, 2);
            float r = rsqrta(n);
            ull r2 = packf2(r, r);
#pragma unroll
            for (int q = 0; q < 4; q++) c2[q] = mul2(v[q], r2);
        }
#pragma unroll
        for (int q = 0; q < 4; q++) z2[q] = c2[q];   // relu is identity (nonneg)
    }

    ulonglong2* p = reinterpret_cast<ulonglong2*>(Zp + (size_t)u * HID);
    p[lane]      = make_ulonglong2(c2[0], c2[1]);
    p[32 + lane] = make_ulonglong2(c2[2], c2[3]);
}

// ---------------- output gather (un-permute) ---------------------------------
__global__ void gather_kernel(const int* __restrict__ users,
                              const int* __restrict__ pos,
                              const int* __restrict__ neg,
                              const float* __restrict__ Zp,
                              float* __restrict__ out)
{
    int r = blockIdx.x;
    int j = threadIdx.x;
    int node;
    if (r < BB)            node = users[r];
    else if (r < 2 * BB)   node = N_USERS + pos[r - BB];
    else                   node = N_USERS + neg[r - 2 * BB];
    out[(size_t)r * HID + j] = Zp[(size_t)node * HID + fpos(j)];
}

// ---------------- launch -----------------------------------------------------
extern "C" void kernel_launch(void* const* d_in, const int* in_sizes, int n_in,
                              void* d_out, int out_size)
{
    const float* X     = (const float*)d_in[0];
    const float* W     = (const float*)d_in[1];
    const float* b     = (const float*)d_in[2];
    const int*   edges = (const int*)d_in[3];
    const int*   users = (const int*)d_in[4];
    const int*   pos   = (const int*)d_in[5];
    const int*   neg   = (const int*)d_in[6];
    float*       out   = (float*)d_out;
    const int* src = edges;
    const int* trg = edges + M_EDGES;

    float* Zp = nullptr;
    cudaGetSymbolAddress((void**)&Zp, g_Zp);

    const int routeSmem = 4 * SLOTS * 128 * (int)sizeof(ull);   // 56KB
    cudaFuncSetAttribute(route_all_kernel,
                         cudaFuncAttributeMaxDynamicSharedMemorySize, routeSmem);
    const int sortSmem = N_USERS * (int)sizeof(int);            // 160KB
    cudaFuncSetAttribute(sort_fused_kernel,
                         cudaFuncAttributeMaxDynamicSharedMemorySize, sortSmem);

    // launch order keeps route_all_kernel as the 4th launch (ncu target)
    gemm_init_kernel<<<N_NODES / RPB, 128>>>(X, W, b, Zp);         // 1 (also zeros g_deg)
    hist_scatter_kernel<<<(M_EDGES + 255) / 256, 256>>>(src, trg);  // 2
    sort_fused_kernel<<<1, 1024, sortSmem>>>();                     // 3
    route_all_kernel<<<N_USERS / 4, 128, routeSmem>>>(Zp);          // 4  <-- profiled
    gather_kernel<<<3 * BB, 256>>>(users, pos, neg, Zp, out);       // 5
}

// round 16
// speedup vs baseline: 1.1710x; 1.0090x over previous
#include <cuda_runtime.h>
#include <cstdint>

#define N_USERS 40000
#define N_ITEMS 60000
#define N_NODES 100000
#define IN_DIM 256
#define HID 256
#define M_EDGES 500000
#define BB 4096
#define NUM_LAYERS 5
#define ROUTIT 7
#define EPS 1e-12f
#define FULL 0xffffffffu
#define STRIDE 96          // CSR slots per user (P(overflow) ~ 0)

typedef unsigned long long ull;

// ---------------- packed f32x2 + misc helpers --------------------------------
__device__ __forceinline__ ull fma2(ull a, ull b, ull c) {
    ull d; asm("fma.rn.f32x2 %0, %1, %2, %3;" : "=l"(d) : "l"(a), "l"(b), "l"(c)); return d;
}
__device__ __forceinline__ ull mul2(ull a, ull b) {
    ull d; asm("mul.rn.f32x2 %0, %1, %2;" : "=l"(d) : "l"(a), "l"(b)); return d;
}
__device__ __forceinline__ ull add2(ull a, ull b) {
    ull d; asm("add.rn.f32x2 %0, %1, %2;" : "=l"(d) : "l"(a), "l"(b)); return d;
}
__device__ __forceinline__ float hsum2(ull v) {
    float lo, hi; asm("mov.b64 {%0, %1}, %2;" : "=f"(lo), "=f"(hi) : "l"(v)); return lo + hi;
}
__device__ __forceinline__ ull packf2(float x, float y) {
    ull r; asm("mov.b64 %0, {%1, %2};" : "=l"(r) : "f"(x), "f"(y)); return r;
}
__device__ __forceinline__ float rcpa(float x) {
    float r; asm("rcp.approx.f32 %0, %1;" : "=f"(r) : "f"(x)); return r;
}
__device__ __forceinline__ float rsqrta(float x) {
    float r; asm("rsqrt.approx.f32 %0, %1;" : "=f"(r) : "f"(x)); return r;
}
__device__ __forceinline__ float ex2a(float x) {
    float r; asm("ex2.approx.f32 %0, %1;" : "=f"(r) : "f"(x)); return r;
}
#define LOG2E 1.44269504f

// permutation: element j (k=j/32, d=j%32) -> lane l=4k+d/8 holds 8 contiguous dims.
__device__ __forceinline__ int fpos(int j) {
    int k = j >> 5, d = j & 31;
    int l = (k << 2) + (d >> 3);
    int jj = d & 7;
    return (jj < 4) ? (4 * l + jj) : (128 + 4 * l + (jj - 4));
}

// ---------------- scratch ----------------------------------------------------
__device__ float g_Zp[(size_t)N_NODES * HID];
__device__ int   g_deg[N_USERS];
__device__ int   g_ctrg[(size_t)N_USERS * STRIDE];
__device__ int   g_bins[64];
__device__ int   g_bcur[64];
__device__ int   g_uorder[N_USERS];

// ---------------- zero (must precede fused gemm+hist) ------------------------
__global__ void zero_kernel()
{
    int i = blockIdx.x * blockDim.x + threadIdx.x;
    if (i < N_USERS) g_deg[i] = 0;
    if (i < 64) g_bins[i] = 0;
}

// ---------------- GEMM + CSR hist/scatter (fused; independent work) ----------
#define RPB 32
#define EDGES_PER_BLOCK 160   // 3125 blocks * 160 = 500000 exactly
__global__ void __launch_bounds__(128)
gemm_init_kernel(const float* __restrict__ X,
                 const float* __restrict__ W,
                 const float* __restrict__ b,
                 const int* __restrict__ src,
                 const int* __restrict__ trg,
                 float* __restrict__ Zp)
{
    // side task: this block's slice of the edge hist/scatter (atomic traffic
    // overlaps with other blocks' FMA phases)
    {
        int ebase = blockIdx.x * EDGES_PER_BLOCK;
        for (int i = threadIdx.x; i < EDGES_PER_BLOCK; i += 128) {
            int ei = ebase + i;
            int s = src[ei];
            int pos = atomicAdd(&g_deg[s], 1);
            if (pos < STRIDE) g_ctrg[(size_t)s * STRIDE + pos] = trg[ei];
        }
    }

    __shared__ ull xs2[RPB / 2][IN_DIM];
    int t = threadIdx.x;
    int j0 = t, j1 = t + 128;
    int row0 = blockIdx.x * RPB;

    for (int idx = t; idx < (RPB / 2) * IN_DIM; idx += 128) {
        int rp = idx >> 8, i = idx & 255;
        float a = X[(size_t)(row0 + 2 * rp) * IN_DIM + i];
        float c = X[(size_t)(row0 + 2 * rp + 1) * IN_DIM + i];
        xs2[rp][i] = packf2(a, c);
    }
    __syncthreads();

    float b0 = b[j0], b1 = b[j1];
    ull acc0[RPB / 2], acc1[RPB / 2];
#pragma unroll
    for (int rp = 0; rp < RPB / 2; rp++) { acc0[rp] = packf2(b0, b0); acc1[rp] = packf2(b1, b1); }

#pragma unroll 4
    for (int i = 0; i < IN_DIM; i++) {
        float w0 = W[(size_t)i * HID + j0];
        float w1 = W[(size_t)i * HID + j1];
        ull wp0 = packf2(w0, w0), wp1 = packf2(w1, w1);
#pragma unroll
        for (int rp = 0; rp < RPB / 2; rp++) {
            ull x = xs2[rp][i];
            acc0[rp] = fma2(x, wp0, acc0[rp]);
            acc1[rp] = fma2(x, wp1, acc1[rp]);
        }
    }

    int f0 = fpos(j0), f1 = fpos(j1);
#pragma unroll
    for (int rp = 0; rp < RPB / 2; rp++) {
        float va[2], vb[2];
        asm("mov.b64 {%0, %1}, %2;" : "=f"(va[0]), "=f"(va[1]) : "l"(acc0[rp]));
        asm("mov.b64 {%0, %1}, %2;" : "=f"(vb[0]), "=f"(vb[1]) : "l"(acc1[rp]));
#pragma unroll
        for (int h = 0; h < 2; h++) {
            float h0 = fmaxf(va[h], 0.f);
            float h1 = fmaxf(vb[h], 0.f);
            float s0 = h0 * h0, s1 = h1 * h1;
#pragma unroll
            for (int o = 16; o > 0; o >>= 1) {
                s0 += __shfl_xor_sync(FULL, s0, o);
                s1 += __shfl_xor_sync(FULL, s1, o);
            }
            float i0 = rcpa(fmaxf(sqrtf(s0), EPS));
            float i1 = rcpa(fmaxf(sqrtf(s1), EPS));
            size_t rowoff = (size_t)(row0 + 2 * rp + h) * HID;
            Zp[rowoff + f0] = h0 * i0;
            Zp[rowoff + f1] = h1 * i1;
        }
    }
}

// ---------------- counting sort of users by degree (descending) --------------
__global__ void deg_hist_kernel()
{
    int u = blockIdx.x * blockDim.x + threadIdx.x;
    if (u < N_USERS) {
        int d = g_deg[u];
        int bin = 63 - (d < 63 ? d : 63);
        atomicAdd(&g_bins[bin], 1);
    }
}

__global__ void bin_scan_kernel()
{
    __shared__ int s[64];
    int t = threadIdx.x;
    int orig = g_bins[t];
    s[t] = orig;
    __syncthreads();
    for (int o = 1; o < 64; o <<= 1) {
        int v = (t >= o) ? s[t - o] : 0;
        __syncthreads();
        s[t] += v;
        __syncthreads();
    }
    g_bcur[t] = s[t] - orig;
}

__global__ void user_sort_kernel()
{
    int u = blockIdx.x * blockDim.x + threadIdx.x;
    if (u < N_USERS) {
        int d = g_deg[u];
        int bin = 63 - (d < 63 ? d : 63);
        int p = atomicAdd(&g_bcur[bin], 1);
        g_uorder[p] = u;
    }
}

// ---------------- mega routing kernel (R13-proven, frozen) --------------------
#define REGE 4
#define SLOTS 14
#define SMCAP (REGE + SLOTS)

// 4 edges; transpose-reduce so each lane owns one (k, edge) pair.
__device__ __forceinline__ void edge_quad_t(const ull A[4], const ull B[4],
                                            const ull C[4], const ull D[4],
                                            const ull c2[4], int sub,
                                            ull aggA[4], ull aggB[4])
{
    ull s0 = mul2(A[0], c2[0]);
    ull s1 = mul2(B[0], c2[0]);
    ull s2 = mul2(C[0], c2[0]);
    ull s3 = mul2(D[0], c2[0]);
#pragma unroll
    for (int q = 1; q < 4; q++) {
        s0 = fma2(A[q], c2[q], s0);
        s1 = fma2(B[q], c2[q], s1);
        s2 = fma2(C[q], c2[q], s2);
        s3 = fma2(D[q], c2[q], s3);
    }
    float p0 = hsum2(s0), p1 = hsum2(s1), p2 = hsum2(s2), p3 = hsum2(s3);
    bool b0 = sub & 1, b1 = sub & 2;
    float sA = b0 ? p0 : p1;
    float sB = b0 ? p2 : p3;
    float rA = __shfl_xor_sync(FULL, sA, 1);
    float rB = __shfl_xor_sync(FULL, sB, 1);
    float q0 = (b0 ? p1 : p0) + rA;
    float q1 = (b0 ? p3 : p2) + rB;
    float sC = b1 ? q0 : q1;
    float rC = __shfl_xor_sync(FULL, sC, 2);
    float S  = (b1 ? q1 : q0) + rC;
    float e = ex2a(S * LOG2E);
    float den = e;
    den += __shfl_xor_sync(FULL, den, 4);
    den += __shfl_xor_sync(FULL, den, 8);
    den += __shfl_xor_sync(FULL, den, 16);
    float w = e * rcpa(den);
    float w0 = __shfl_sync(FULL, w, 0, 4);
    float w1 = __shfl_sync(FULL, w, 1, 4);
    float w2 = __shfl_sync(FULL, w, 2, 4);
    float w3 = __shfl_sync(FULL, w, 3, 4);
    ull w02 = packf2(w0, w0), w12 = packf2(w1, w1);
    ull w22 = packf2(w2, w2), w32 = packf2(w3, w3);
#pragma unroll
    for (int q = 0; q < 4; q++) {
        aggA[q] = fma2(A[q], w02, aggA[q]);
        aggB[q] = fma2(B[q], w12, aggB[q]);
        aggA[q] = fma2(C[q], w22, aggA[q]);
        aggB[q] = fma2(D[q], w32, aggB[q]);
    }
}

// 8 edges: TWO independent transpose-reduce chains fully interleaved.
__device__ __forceinline__ void edge_oct_t(const ull A[4], const ull B[4],
                                           const ull C[4], const ull D[4],
                                           const ull E[4], const ull F[4],
                                           const ull G[4], const ull H[4],
                                           const ull c2[4], int sub,
                                           ull aggA[4], ull aggB[4])
{
    ull s0 = mul2(A[0], c2[0]);
    ull s1 = mul2(B[0], c2[0]);
    ull s2 = mul2(C[0], c2[0]);
    ull s3 = mul2(D[0], c2[0]);
    ull s4 = mul2(E[0], c2[0]);
    ull s5 = mul2(F[0], c2[0]);
    ull s6 = mul2(G[0], c2[0]);
    ull s7 = mul2(H[0], c2[0]);
#pragma unroll
    for (int q = 1; q < 4; q++) {
        s0 = fma2(A[q], c2[q], s0);
        s1 = fma2(B[q], c2[q], s1);
        s2 = fma2(C[q], c2[q], s2);
        s3 = fma2(D[q], c2[q], s3);
        s4 = fma2(E[q], c2[q], s4);
        s5 = fma2(F[q], c2[q], s5);
        s6 = fma2(G[q], c2[q], s6);
        s7 = fma2(H[q], c2[q], s7);
    }
    float p0 = hsum2(s0), p1 = hsum2(s1), p2 = hsum2(s2), p3 = hsum2(s3);
    float p4 = hsum2(s4), p5 = hsum2(s5), p6 = hsum2(s6), p7 = hsum2(s7);
    bool b0 = sub & 1, b1 = sub & 2;
    float sA = b0 ? p0 : p1;
    float sB = b0 ? p2 : p3;
    float sE = b0 ? p4 : p5;
    float sF = b0 ? p6 : p7;
    float rA = __shfl_xor_sync(FULL, sA, 1);
    float rB = __shfl_xor_sync(FULL, sB, 1);
    float rE = __shfl_xor_sync(FULL, sE, 1);
    float rF = __shfl_xor_sync(FULL, sF, 1);
    float q0 = (b0 ? p1 : p0) + rA;
    float q1 = (b0 ? p3 : p2) + rB;
    float q4 = (b0 ? p5 : p4) + rE;
    float q5 = (b0 ? p7 : p6) + rF;
    float sC = b1 ? q0 : q1;
    float sG = b1 ? q4 : q5;
    float rC = __shfl_xor_sync(FULL, sC, 2);
    float rG = __shfl_xor_sync(FULL, sG, 2);
    float S1 = (b1 ? q1 : q0) + rC;
    float S2 = (b1 ? q5 : q4) + rG;
    float e1 = ex2a(S1 * LOG2E);
    float e2 = ex2a(S2 * LOG2E);
    float d1 = e1, d2 = e2;
    d1 += __shfl_xor_sync(FULL, d1, 4);   d2 += __shfl_xor_sync(FULL, d2, 4);
    d1 += __shfl_xor_sync(FULL, d1, 8);   d2 += __shfl_xor_sync(FULL, d2, 8);
    d1 += __shfl_xor_sync(FULL, d1, 16);  d2 += __shfl_xor_sync(FULL, d2, 16);
    float w1 = e1 * rcpa(d1);
    float w2 = e2 * rcpa(d2);
    float wa = __shfl_sync(FULL, w1, 0, 4);
    float wb = __shfl_sync(FULL, w1, 1, 4);
    float wc = __shfl_sync(FULL, w1, 2, 4);
    float wd = __shfl_sync(FULL, w1, 3, 4);
    float we = __shfl_sync(FULL, w2, 0, 4);
    float wf = __shfl_sync(FULL, w2, 1, 4);
    float wg = __shfl_sync(FULL, w2, 2, 4);
    float wh = __shfl_sync(FULL, w2, 3, 4);
    ull wa2 = packf2(wa, wa), wb2 = packf2(wb, wb);
    ull wc2 = packf2(wc, wc), wd2 = packf2(wd, wd);
    ull we2 = packf2(we, we), wf2 = packf2(wf, wf);
    ull wg2 = packf2(wg, wg), wh2 = packf2(wh, wh);
#pragma unroll
    for (int q = 0; q < 4; q++) {
        aggA[q] = fma2(A[q], wa2, aggA[q]);
        aggB[q] = fma2(B[q], wb2, aggB[q]);
        aggA[q] = fma2(C[q], wc2, aggA[q]);
        aggB[q] = fma2(D[q], wd2, aggB[q]);
        aggA[q] = fma2(E[q], we2, aggA[q]);
        aggB[q] = fma2(F[q], wf2, aggB[q]);
        aggA[q] = fma2(G[q], wg2, aggA[q]);
        aggB[q] = fma2(H[q], wh2, aggB[q]);
    }
}

// 2 edges, chains interleaved (tail path)
__device__ __forceinline__ void edge_pair(const ull A[4], const ull B[4],
                                          const ull c2[4],
                                          ull aggA[4], ull aggB[4])
{
    ull sa2 = mul2(A[0], c2[0]);
    ull sb2 = mul2(B[0], c2[0]);
#pragma unroll
    for (int q = 1; q < 4; q++) {
        sa2 = fma2(A[q], c2[q], sa2);
        sb2 = fma2(B[q], c2[q], sb2);
    }
    float sa = hsum2(sa2), sb = hsum2(sb2);
    sa += __shfl_xor_sync(FULL, sa, 1);  sb += __shfl_xor_sync(FULL, sb, 1);
    sa += __shfl_xor_sync(FULL, sa, 2);  sb += __shfl_xor_sync(FULL, sb, 2);
    float ea = ex2a(sa * LOG2E), eb = ex2a(sb * LOG2E);
    float da = ea, db = eb;
    da += __shfl_xor_sync(FULL, da, 4);   db += __shfl_xor_sync(FULL, db, 4);
    da += __shfl_xor_sync(FULL, da, 8);   db += __shfl_xor_sync(FULL, db, 8);
    da += __shfl_xor_sync(FULL, da, 16);  db += __shfl_xor_sync(FULL, db, 16);
    float wa = ea * rcpa(da), wb = eb * rcpa(db);
    ull wa2 = packf2(wa, wa), wb2 = packf2(wb, wb);
#pragma unroll
    for (int q = 0; q < 4; q++) {
        aggA[q] = fma2(A[q], wa2, aggA[q]);
        aggB[q] = fma2(B[q], wb2, aggB[q]);
    }
}

// single edge (tail / overflow path)
__device__ __forceinline__ void edge_one(const ull A[4], const ull c2[4], ull aggA[4])
{
    ull sa2 = mul2(A[0], c2[0]);
#pragma unroll
    for (int q = 1; q < 4; q++) sa2 = fma2(A[q], c2[q], sa2);
    float sa = hsum2(sa2);
    sa += __shfl_xor_sync(FULL, sa, 1);
    sa += __shfl_xor_sync(FULL, sa, 2);
    float ea = ex2a(sa * LOG2E);
    float da = ea;
    da += __shfl_xor_sync(FULL, da, 4);
    da += __shfl_xor_sync(FULL, da, 8);
    da += __shfl_xor_sync(FULL, da, 16);
    float wa = ea * rcpa(da);
    ull wa2 = packf2(wa, wa);
#pragma unroll
    for (int q = 0; q < 4; q++) aggA[q] = fma2(A[q], wa2, aggA[q]);
}

__device__ __forceinline__ void load_row_g(const float* __restrict__ Zp, int node,
                                           int lane, ull X[4])
{
    const ulonglong2* p = reinterpret_cast<const ulonglong2*>(Zp + (size_t)node * HID);
    ulonglong2 a = p[lane];
    ulonglong2 c = p[32 + lane];
    X[0] = a.x; X[1] = a.y; X[2] = c.x; X[3] = c.y;
}

__device__ __forceinline__ void load_row_s(const ull* slab, int slot, int lane, ull X[4])
{
    const ulonglong2* p = reinterpret_cast<const ulonglong2*>(slab + (size_t)slot * 128);
    ulonglong2 a = p[lane], c = p[32 + lane];
    X[0] = a.x; X[1] = a.y; X[2] = c.x; X[3] = c.y;
}

extern __shared__ ull sh_slab[];   // 4 warps * SLOTS * 128 ull = 56KB

__global__ void __launch_bounds__(128, 4)
route_all_kernel(float* __restrict__ Zp)
{
    int lane = threadIdx.x & 31;
    int winb = threadIdx.x >> 5;
    int sub  = lane & 3;
    int u = g_uorder[blockIdx.x * 4 + winb];
    ull* slab = sh_slab + (size_t)winb * SLOTS * 128;

    int beg = u * STRIDE;
    int deg = g_deg[u];
    if (deg > STRIDE) deg = STRIDE;
    int nreg = deg < REGE ? deg : REGE;
    int nsm  = deg < SMCAP ? deg : SMCAP;
    int nsmem = nsm - REGE;
    if (nsmem < 0) nsmem = 0;

    ull z2[4], c2[4];
    load_row_g(Zp, u, lane, z2);

    ull er[REGE][4];
#pragma unroll
    for (int e = 0; e < REGE; e++) {
        if (e < nreg) {
            int t = g_ctrg[beg + e];
            load_row_g(Zp, t, lane, er[e]);
        }
    }
    for (int e = 0; e < nsmem; e++) {
        int t = g_ctrg[beg + REGE + e];
        ull X[4];
        load_row_g(Zp, t, lane, X);
        ulonglong2* p = reinterpret_cast<ulonglong2*>(slab + (size_t)e * 128);
        p[lane]      = make_ulonglong2(X[0], X[1]);
        p[32 + lane] = make_ulonglong2(X[2], X[3]);
    }

#pragma unroll
    for (int q = 0; q < 4; q++) c2[q] = z2[q];

    for (int layer = 0; layer < NUM_LAYERS; layer++) {
        for (int it = 0; it < ROUTIT; it++) {
            ull aggA[4] = {0, 0, 0, 0};
            ull aggB[4] = {0, 0, 0, 0};
            int e = 0;   // smem slot cursor
            if (nreg == REGE) {
                if (nsmem >= 4) {
                    ull S0[4], S1[4], S2[4], S3[4];
                    load_row_s(slab, 0, lane, S0);
                    load_row_s(slab, 1, lane, S1);
                    load_row_s(slab, 2, lane, S2);
                    load_row_s(slab, 3, lane, S3);
                    edge_oct_t(er[0], er[1], er[2], er[3],
                               S0, S1, S2, S3, c2, sub, aggA, aggB);
                    e = 4;
                } else {
                    edge_quad_t(er[0], er[1], er[2], er[3], c2, sub, aggA, aggB);
                }
            } else if (nreg == 3) {
                edge_pair(er[0], er[1], c2, aggA, aggB);
                edge_one(er[2], c2, aggA);
            } else if (nreg == 2) {
                edge_pair(er[0], er[1], c2, aggA, aggB);
            } else if (nreg == 1) {
                edge_one(er[0], c2, aggA);
            }
            for (; e + 3 < nsmem; e += 4) {
                ull A[4], B[4], C[4], D[4];
                load_row_s(slab, e,     lane, A);
                load_row_s(slab, e + 1, lane, B);
                load_row_s(slab, e + 2, lane, C);
                load_row_s(slab, e + 3, lane, D);
                edge_quad_t(A, B, C, D, c2, sub, aggA, aggB);
            }
            if (e + 1 < nsmem) {
                ull A[4], B[4];
                load_row_s(slab, e,     lane, A);
                load_row_s(slab, e + 1, lane, B);
                edge_pair(A, B, c2, aggA, aggB);
                e += 2;
            }
            if (e < nsmem) {
                ull A[4];
                load_row_s(slab, e, lane, A);
                edge_one(A, c2, aggA);
            }
            for (int eg = SMCAP; eg < deg; eg++) {
                int t = g_ctrg[beg + eg];
                ull A[4];
                load_row_g(Zp, t, lane, A);
                edge_one(A, c2, aggA);
            }
            ull v[4];
#pragma unroll
            for (int q = 0; q < 4; q++) v[q] = add2(z2[q], add2(aggA[q], aggB[q]));
            ull n2 = mul2(v[0], v[0]);
#pragma unroll
            for (int q = 1; q < 4; q++) n2 = fma2(v[q], v[q], n2);
            float n = hsum2(n2);
            n += __shfl_xor_sync(FULL, n, 1);
            n += __shfl_xor_sync(FULL, n, 2);
            float r = rsqrta(n);
            ull r2 = packf2(r, r);
#pragma unroll
            for (int q = 0; q < 4; q++) c2[q] = mul2(v[q], r2);
        }
#pragma unroll
        for (int q = 0; q < 4; q++) z2[q] = c2[q];   // relu is identity (nonneg)
    }

    ulonglong2* p = reinterpret_cast<ulonglong2*>(Zp + (size_t)u * HID);
    p[lane]      = make_ulonglong2(c2[0], c2[1]);
    p[32 + lane] = make_ulonglong2(c2[2], c2[3]);
}

// ---------------- output gather (un-permute) ---------------------------------
__global__ void gather_kernel(const int* __restrict__ users,
                              const int* __restrict__ pos,
                              const int* __restrict__ neg,
                              const float* __restrict__ Zp,
                              float* __restrict__ out)
{
    int r = blockIdx.x;
    int j = threadIdx.x;
    int node;
    if (r < BB)            node = users[r];
    else if (r < 2 * BB)   node = N_USERS + pos[r - BB];
    else                   node = N_USERS + neg[r - 2 * BB];
    out[(size_t)r * HID + j] = Zp[(size_t)node * HID + fpos(j)];
}

// ---------------- launch -----------------------------------------------------
extern "C" void kernel_launch(void* const* d_in, const int* in_sizes, int n_in,
                              void* d_out, int out_size)
{
    const float* X     = (const float*)d_in[0];
    const float* W     = (const float*)d_in[1];
    const float* b     = (const float*)d_in[2];
    const int*   edges = (const int*)d_in[3];
    const int*   users = (const int*)d_in[4];
    const int*   pos   = (const int*)d_in[5];
    const int*   neg   = (const int*)d_in[6];
    float*       out   = (float*)d_out;
    const int* src = edges;
    const int* trg = edges + M_EDGES;

    float* Zp = nullptr;
    cudaGetSymbolAddress((void**)&Zp, g_Zp);

    const int routeSmem = 4 * SLOTS * 128 * (int)sizeof(ull);   // 56KB
    cudaFuncSetAttribute(route_all_kernel,
                         cudaFuncAttributeMaxDynamicSharedMemorySize, routeSmem);

    zero_kernel<<<(N_USERS + 255) / 256, 256>>>();                      // 1
    gemm_init_kernel<<<N_NODES / RPB, 128>>>(X, W, b, src, trg, Zp);    // 2 (+ hist/scatter)
    deg_hist_kernel<<<(N_USERS + 255) / 256, 256>>>();                  // 3
    bin_scan_kernel<<<1, 64>>>();                                       // 4
    user_sort_kernel<<<(N_USERS + 255) / 256, 256>>>();                 // 5
    route_all_kernel<<<N_USERS / 4, 128, routeSmem>>>(Zp);              // 6
    gather_kernel<<<3 * BB, 256>>>(users, pos, neg, Zp, out);           // 7
}